// round 4
// baseline (speedup 1.0000x reference)
#include <cuda_runtime.h>
#include <cuda_bf16.h>
#include <cstdint>
#include <math.h>

// Problem constants
#define BATCH  128
#define HEADS  4
#define SEQLEN 256
#define EMB    64
#define DQK    64
#define LHEAD  64
#define KDIM   4096   // LHEAD * EMB
#define ODIM   4096   // LHEAD * DQK
#define NTOT   (BATCH * HEADS * KDIM)   // 2097152 (== BATCH*SEQLEN*EMB)

// ---------------- scratch (device globals; no allocation allowed) ----------------
__device__ __align__(16) __nv_bfloat16 g_Ahi[NTOT];
__device__ __align__(16) __nv_bfloat16 g_Alo[NTOT];
__device__ __align__(16) float g_QKV[12 * BATCH * ODIM];   // [t*4+h][b][o]

// ---------------- kernel 1: split fp32 activations into bf16 hi/lo ----------------
__global__ void split_bf16_kernel(const float* __restrict__ x) {
    int i = blockIdx.x * blockDim.x + threadIdx.x;   // float4 index; grid covers NTOT/4 exactly
    float4 v = reinterpret_cast<const float4*>(x)[i];
    __nv_bfloat16 h0 = __float2bfloat16(v.x);
    __nv_bfloat16 h1 = __float2bfloat16(v.y);
    __nv_bfloat16 h2 = __float2bfloat16(v.z);
    __nv_bfloat16 h3 = __float2bfloat16(v.w);
    __nv_bfloat16 l0 = __float2bfloat16(v.x - __bfloat162float(h0));
    __nv_bfloat16 l1 = __float2bfloat16(v.y - __bfloat162float(h1));
    __nv_bfloat16 l2 = __float2bfloat16(v.z - __bfloat162float(h2));
    __nv_bfloat16 l3 = __float2bfloat16(v.w - __bfloat162float(h3));
    __nv_bfloat162* ph = reinterpret_cast<__nv_bfloat162*>(g_Ahi);
    __nv_bfloat162* pl = reinterpret_cast<__nv_bfloat162*>(g_Alo);
    ph[2 * i]     = __halves2bfloat162(h0, h1);
    ph[2 * i + 1] = __halves2bfloat162(h2, h3);
    pl[2 * i]     = __halves2bfloat162(l0, l1);
    pl[2 * i + 1] = __halves2bfloat162(l2, l3);
}

// ---------------- kernel 2: split-bf16 QKV projection GEMMs ----------------
// C[b, o] = sum_i A[b,i] * W[o,i] + bias[o]   for each (t in {Q,K,V}, h in 0..3)
// Tile: BM=128 (all of batch), BN=128, BK=32. 8 warps, each 64x32.
// smem per stage (bf16 elements): Ahi[128][40] Alo[128][40] Whi[128][40] Wlo[128][40]
#define SM_STRIDE 40           // 32 + 8 pad -> conflict-free ldmatrix
#define SM_TILE   (128 * SM_STRIDE)   // 5120
#define SM_STAGE  (4 * SM_TILE)       // 20480 elements = 40960 bytes
#define GEMM_SMEM (2 * SM_STAGE * 2)  // 81920 bytes

#define LDM_X4(R, ADDR) \
  asm volatile("ldmatrix.sync.aligned.m8n8.x4.shared.b16 {%0,%1,%2,%3}, [%4];" \
    : "=r"((R)[0]), "=r"((R)[1]), "=r"((R)[2]), "=r"((R)[3]) : "r"(ADDR))

#define MMA_BF16(C, A, Bv) \
  asm volatile("mma.sync.aligned.m16n8k16.row.col.f32.bf16.bf16.f32 " \
    "{%0,%1,%2,%3},{%4,%5,%6,%7},{%8,%9},{%0,%1,%2,%3};" \
    : "+f"((C)[0]), "+f"((C)[1]), "+f"((C)[2]), "+f"((C)[3]) \
    : "r"((A)[0]), "r"((A)[1]), "r"((A)[2]), "r"((A)[3]), "r"((Bv)[0]), "r"((Bv)[1]))

__global__ void __launch_bounds__(256, 1)
qkv_gemm_kernel(const float* __restrict__ WQp, const float* __restrict__ bQp,
                const float* __restrict__ WKp, const float* __restrict__ bKp,
                const float* __restrict__ WVp, const float* __restrict__ bVp)
{
    extern __shared__ __nv_bfloat16 sm[];
    const int tid  = threadIdx.x;
    const int lane = tid & 31;
    const int wid  = tid >> 5;
    const int t = blockIdx.y >> 2;
    const int h = blockIdx.y & 3;
    const float* Wp = (t == 0) ? WQp : (t == 1) ? WKp : WVp;
    const float* bp = ((t == 0) ? bQp : (t == 1) ? bKp : bVp) + h * ODIM;
    const float* Wg = Wp + ((size_t)h * ODIM + (size_t)blockIdx.x * 128) * (size_t)KDIM;
    const __nv_bfloat16* Ahg = g_Ahi + h * KDIM;   // row stride HEADS*KDIM = 16384
    const __nv_bfloat16* Alg = g_Alo + h * KDIM;

    const int Rm = (wid >> 2) * 64;   // warp M offset (0 or 64)
    const int Cn = (wid & 3) * 32;    // warp N offset (0,32,64,96)
    const uint32_t smem_u = (uint32_t)__cvta_generic_to_shared(sm);

    float acc[4][4][4];
#pragma unroll
    for (int i0 = 0; i0 < 4; i0++)
#pragma unroll
        for (int i1 = 0; i1 < 4; i1++)
#pragma unroll
            for (int i2 = 0; i2 < 4; i2++) acc[i0][i1][i2] = 0.f;

    float4 wreg[4];
    uint4  ahreg[2], alreg[2];

#define GEMM_LDG(K0) do { \
    _Pragma("unroll") \
    for (int j = 0; j < 4; j++) { \
        int f = tid + 256 * j; int rr = f >> 3; int cc = (f & 7) * 4; \
        wreg[j] = *reinterpret_cast<const float4*>(Wg + (size_t)rr * KDIM + (K0) + cc); \
    } \
    _Pragma("unroll") \
    for (int j = 0; j < 2; j++) { \
        int cI = tid + 256 * j; int rr = cI >> 2; int sg = (cI & 3) * 8; \
        ahreg[j] = *reinterpret_cast<const uint4*>(Ahg + (size_t)rr * (HEADS * KDIM) + (K0) + sg); \
        alreg[j] = *reinterpret_cast<const uint4*>(Alg + (size_t)rr * (HEADS * KDIM) + (K0) + sg); \
    } \
} while (0)

#define GEMM_STS(S) do { \
    __nv_bfloat16* s_ahi = sm + (S) * SM_STAGE; \
    __nv_bfloat16* s_alo = s_ahi + SM_TILE; \
    __nv_bfloat16* s_whi = s_ahi + 2 * SM_TILE; \
    __nv_bfloat16* s_wlo = s_ahi + 3 * SM_TILE; \
    _Pragma("unroll") \
    for (int j = 0; j < 4; j++) { \
        int f = tid + 256 * j; int rr = f >> 3; int cc = (f & 7) * 4; \
        float4 v = wreg[j]; \
        __nv_bfloat162 ph0 = __floats2bfloat162_rn(v.x, v.y); \
        __nv_bfloat162 ph1 = __floats2bfloat162_rn(v.z, v.w); \
        float2 f0 = __bfloat1622float2(ph0); \
        float2 f1 = __bfloat1622float2(ph1); \
        __nv_bfloat162 pl0 = __floats2bfloat162_rn(v.x - f0.x, v.y - f0.y); \
        __nv_bfloat162 pl1 = __floats2bfloat162_rn(v.z - f1.x, v.w - f1.y); \
        uint2 uh; uh.x = reinterpret_cast<uint32_t&>(ph0); uh.y = reinterpret_cast<uint32_t&>(ph1); \
        uint2 ul; ul.x = reinterpret_cast<uint32_t&>(pl0); ul.y = reinterpret_cast<uint32_t&>(pl1); \
        *reinterpret_cast<uint2*>(s_whi + rr * SM_STRIDE + cc) = uh; \
        *reinterpret_cast<uint2*>(s_wlo + rr * SM_STRIDE + cc) = ul; \
    } \
    _Pragma("unroll") \
    for (int j = 0; j < 2; j++) { \
        int cI = tid + 256 * j; int rr = cI >> 2; int sg = (cI & 3) * 8; \
        uint2 u0; u0.x = ahreg[j].x; u0.y = ahreg[j].y; \
        uint2 u1; u1.x = ahreg[j].z; u1.y = ahreg[j].w; \
        *reinterpret_cast<uint2*>(s_ahi + rr * SM_STRIDE + sg) = u0; \
        *reinterpret_cast<uint2*>(s_ahi + rr * SM_STRIDE + sg + 4) = u1; \
        uint2 v0; v0.x = alreg[j].x; v0.y = alreg[j].y; \
        uint2 v1; v1.x = alreg[j].z; v1.y = alreg[j].w; \
        *reinterpret_cast<uint2*>(s_alo + rr * SM_STRIDE + sg) = v0; \
        *reinterpret_cast<uint2*>(s_alo + rr * SM_STRIDE + sg + 4) = v1; \
    } \
} while (0)

#define GEMM_COMPUTE(S) do { \
    uint32_t aB  = smem_u + (uint32_t)(S) * SM_STAGE * 2; \
    uint32_t alB = aB + SM_TILE * 2; \
    uint32_t wB  = aB + 2 * SM_TILE * 2; \
    uint32_t wlB = aB + 3 * SM_TILE * 2; \
    _Pragma("unroll") \
    for (int ks = 0; ks < 2; ks++) { \
        uint32_t ah[4][4], al[4][4], bh[4][2], bl[4][2]; \
        int arl = lane & 15; \
        int ako = ks * 16 + ((lane >> 4) << 3); \
        _Pragma("unroll") \
        for (int mi = 0; mi < 4; mi++) { \
            uint32_t off = (uint32_t)((Rm + mi * 16 + arl) * SM_STRIDE + ako) * 2; \
            LDM_X4(ah[mi], aB + off); \
            LDM_X4(al[mi], alB + off); \
        } \
        int bnr = ((lane >> 4) << 3) + (lane & 7); \
        int bko = ks * 16 + (((lane >> 3) & 1) << 3); \
        _Pragma("unroll") \
        for (int jj = 0; jj < 2; jj++) { \
            uint32_t off = (uint32_t)((Cn + jj * 16 + bnr) * SM_STRIDE + bko) * 2; \
            uint32_t r4[4]; \
            LDM_X4(r4, wB + off); \
            bh[2 * jj][0] = r4[0]; bh[2 * jj][1] = r4[1]; \
            bh[2 * jj + 1][0] = r4[2]; bh[2 * jj + 1][1] = r4[3]; \
            LDM_X4(r4, wlB + off); \
            bl[2 * jj][0] = r4[0]; bl[2 * jj][1] = r4[1]; \
            bl[2 * jj + 1][0] = r4[2]; bl[2 * jj + 1][1] = r4[3]; \
        } \
        _Pragma("unroll") \
        for (int mi = 0; mi < 4; mi++) \
        _Pragma("unroll") \
        for (int nj = 0; nj < 4; nj++) { \
            MMA_BF16(acc[mi][nj], ah[mi], bh[nj]); \
            MMA_BF16(acc[mi][nj], ah[mi], bl[nj]); \
            MMA_BF16(acc[mi][nj], al[mi], bh[nj]); \
        } \
    } \
} while (0)

    // prologue
    GEMM_LDG(0);
    GEMM_STS(0);
    const int NK = KDIM / 32;   // 128
    for (int kt = 0; kt < NK; kt++) {
        __syncthreads();
        if (kt + 1 < NK) GEMM_LDG((kt + 1) * 32);
        GEMM_COMPUTE(kt & 1);
        if (kt + 1 < NK) GEMM_STS((kt + 1) & 1);
    }

    // epilogue: add bias, store fp32 Q/K/V to scratch
    const int g   = lane >> 2;
    const int tig = lane & 3;
    float* outB = g_QKV + (size_t)blockIdx.y * 128 * ODIM;
    const int colBase = blockIdx.x * 128 + Cn;
#pragma unroll
    for (int nj = 0; nj < 4; nj++) {
        int col = colBase + nj * 8 + tig * 2;
        float b0 = bp[col];
        float b1 = bp[col + 1];
#pragma unroll
        for (int mi = 0; mi < 4; mi++) {
            int r0 = Rm + mi * 16 + g;
            float2 v0; v0.x = acc[mi][nj][0] + b0; v0.y = acc[mi][nj][1] + b1;
            float2 v1; v1.x = acc[mi][nj][2] + b0; v1.y = acc[mi][nj][3] + b1;
            *reinterpret_cast<float2*>(outB + (size_t)r0 * ODIM + col) = v0;
            *reinterpret_cast<float2*>(outB + (size_t)(r0 + 8) * ODIM + col) = v1;
        }
    }
}

// ---------------- kernel 3: local attention (fp32), softmax over QUERY axis ----------------
#define SPAD 72   // padded row stride (floats); float4-aligned, conflict-free
#define ATTN_SMEM ((3 * 64 * SPAD + 64 * 64) * 4)

__global__ void __launch_bounds__(256)
attn_kernel(float* __restrict__ out)
{
    extern __shared__ float smf[];
    float* Qs = smf;                       // [64][SPAD]
    float* Ks = smf + 64 * SPAD;           // [64][SPAD]
    float* Ss = smf + 2 * 64 * SPAD;       // [64][SPAD]
    float* Vs = smf + 3 * 64 * SPAD;       // [64][64]

    const int b = blockIdx.x >> 2;
    const int h = blockIdx.x & 3;
    const int tid = threadIdx.x;
    const float* Qg = g_QKV + ((size_t)(0 * 4 + h) * BATCH + b) * ODIM;
    const float* Kg = g_QKV + ((size_t)(1 * 4 + h) * BATCH + b) * ODIM;
    const float* Vg = g_QKV + ((size_t)(2 * 4 + h) * BATCH + b) * ODIM;

#pragma unroll
    for (int j = 0; j < 4; j++) {
        int f = tid + 256 * j;
        int r = f >> 4;
        int c = (f & 15) * 4;
        float4 q = *reinterpret_cast<const float4*>(Qg + r * 64 + c);
        float4 k = *reinterpret_cast<const float4*>(Kg + r * 64 + c);
        float4 v = *reinterpret_cast<const float4*>(Vg + r * 64 + c);
        *reinterpret_cast<float4*>(Qs + r * SPAD + c) = q;
        *reinterpret_cast<float4*>(Ks + r * SPAD + c) = k;
        *reinterpret_cast<float4*>(Vs + r * 64 + c) = v;
    }
    __syncthreads();

    const int tx = tid & 15, ty = tid >> 4;
    const int q0 = ty * 4, k0 = tx * 4;

    // scores: each thread computes a 4x4 (q,k) tile
    float s[4][4];
#pragma unroll
    for (int i = 0; i < 4; i++)
#pragma unroll
        for (int j = 0; j < 4; j++) s[i][j] = 0.f;

    for (int d = 0; d < 64; d++) {
        float qv[4], kv[4];
#pragma unroll
        for (int i = 0; i < 4; i++) qv[i] = Qs[(q0 + i) * SPAD + d];
#pragma unroll
        for (int j = 0; j < 4; j++) kv[j] = Ks[(k0 + j) * SPAD + d];
#pragma unroll
        for (int i = 0; i < 4; i++)
#pragma unroll
            for (int j = 0; j < 4; j++) s[i][j] = fmaf(qv[i], kv[j], s[i][j]);
    }
#pragma unroll
    for (int i = 0; i < 4; i++)
#pragma unroll
        for (int j = 0; j < 4; j++) {
            int qq = q0 + i, kk = k0 + j;
            float v = s[i][j];
            if (kk > qq) v -= 1e20f;        // mask above diagonal, exactly as reference
            Ss[qq * SPAD + kk] = v;
        }
    __syncthreads();

    // softmax over QUERY axis (per column k) — matches reference axis=2
    if (tid < 64) {
        int kk = tid;
        float m = -3.4e38f;
        for (int q = 0; q < 64; q++) m = fmaxf(m, Ss[q * SPAD + kk]);
        float sum = 0.f;
        for (int q = 0; q < 64; q++) {
            float e = expf(Ss[q * SPAD + kk] - m);
            Ss[q * SPAD + kk] = e;
            sum += e;
        }
        float inv = 1.f / sum;
        for (int q = 0; q < 64; q++) Ss[q * SPAD + kk] *= inv;
    }
    __syncthreads();

    // Z[q,d] = sum_k attn[q,k] * V[k,d]; thread computes 4x4 (q,d) tile
    const int d0 = tx * 4;
    float z[4][4];
#pragma unroll
    for (int i = 0; i < 4; i++)
#pragma unroll
        for (int j = 0; j < 4; j++) z[i][j] = 0.f;

    for (int k = 0; k < 64; k++) {
        float av[4], vv[4];
#pragma unroll
        for (int i = 0; i < 4; i++) av[i] = Ss[(q0 + i) * SPAD + k];
#pragma unroll
        for (int j = 0; j < 4; j++) vv[j] = Vs[k * 64 + d0 + j];
#pragma unroll
        for (int i = 0; i < 4; i++)
#pragma unroll
            for (int j = 0; j < 4; j++) z[i][j] = fmaf(av[i], vv[j], z[i][j]);
    }

    float* og = out + ((size_t)b * SEQLEN + h * LHEAD) * DQK;
#pragma unroll
    for (int i = 0; i < 4; i++) {
        float4 o4;
        o4.x = z[i][0] * 0.125f;
        o4.y = z[i][1] * 0.125f;
        o4.z = z[i][2] * 0.125f;
        o4.w = z[i][3] * 0.125f;
        *reinterpret_cast<float4*>(og + (q0 + i) * 64 + d0) = o4;
    }
}

// ---------------- launch ----------------
extern "C" void kernel_launch(void* const* d_in, const int* in_sizes, int n_in,
                              void* d_out, int out_size) {
    const float* seq = (const float*)d_in[0];
    const float* WQ  = (const float*)d_in[1];
    const float* bQ  = (const float*)d_in[2];
    const float* WK  = (const float*)d_in[3];
    const float* bK  = (const float*)d_in[4];
    const float* WV  = (const float*)d_in[5];
    const float* bV  = (const float*)d_in[6];
    float* out = (float*)d_out;

    cudaFuncSetAttribute(qkv_gemm_kernel, cudaFuncAttributeMaxDynamicSharedMemorySize, GEMM_SMEM);
    cudaFuncSetAttribute(attn_kernel, cudaFuncAttributeMaxDynamicSharedMemorySize, ATTN_SMEM);

    split_bf16_kernel<<<NTOT / 4 / 256, 256>>>(seq);
    qkv_gemm_kernel<<<dim3(32, 12), 256, GEMM_SMEM>>>(WQ, bQ, WK, bK, WV, bV);
    attn_kernel<<<BATCH * HEADS, 256, ATTN_SMEM>>>(out);
}